// round 13
// baseline (speedup 1.0000x reference)
#include <cuda_runtime.h>
#include <cuda_fp16.h>
#include <math.h>
#include <stdint.h>

// ---------------------------------------------------------------------------
// Problem constants: B=2, T=2048 -> Tt=4096 tokens, D=2048, F=2048, E=8, K=2
// All four GEMMs share K = 2048.
// ---------------------------------------------------------------------------
#define TT      4096
#define DDIM    2048
#define FDIM    2048
#define TWO_F   4096
#define NEXP    8
#define NPAD    9216          // 72 row-blocks of 128 (8192 assignments + padding)
#define NRB     72

#define NC      32            // K chunks (2048 / 64)
#define SROW_H  72            // padded smem row stride (halves): 144B/row
#define ASTG_H  (128 * SROW_H)   // A stage halves (128 rows)
#define BSTG_H  (128 * SROW_H)   // B stage halves (128 rows)
#define STG_H   (ASTG_H + BSTG_H)
#define NSTAGE  3
#define SMEM_BYTES (NSTAGE * STG_H * 2)   // 110592 -> 2 CTAs/SM

// ------------------------- device scratch (no cudaMalloc allowed) ----------
__device__ __half g_shared_act[(size_t)TT * FDIM];       // 16 MB
__device__ __half g_rout_act  [(size_t)NPAD * FDIM];     // 36 MB
__device__ __half g_gathA     [(size_t)NPAD * DDIM];     // 36 MB
__device__ __half g_xh        [(size_t)TT * DDIM];       // 16 MB (fp16 x)
__device__ __half g_w13h      [(size_t)TWO_F * DDIM];    // 16 MB
__device__ __half g_w2h       [(size_t)DDIM * FDIM];     // 8 MB
__device__ __half g_rw13h     [(size_t)NEXP * TWO_F * DDIM];  // 128 MB
__device__ __half g_rw2h      [(size_t)NEXP * DDIM * FDIM];   // 64 MB
__device__ int    g_count[NEXP];
__device__ int    g_tok_list [NEXP * TT];
__device__ float  g_gate_list[NEXP * TT];
__device__ int    g_comp_tok [NPAD];
__device__ float  g_comp_gate[NPAD];
__device__ int    g_rb_expert[NRB];

// ------------------------- helpers -----------------------------------------
__device__ __forceinline__ uint32_t smem_u32(const void* p) {
    uint32_t a;
    asm("{ .reg .u64 t; cvta.to.shared.u64 t, %1; cvt.u32.u64 %0, t; }"
        : "=r"(a) : "l"(p));
    return a;
}
__device__ __forceinline__ void cp16(uint32_t dst, const void* src) {
    asm volatile("cp.async.cg.shared.global [%0], [%1], 16;" :: "r"(dst), "l"(src));
}
__device__ __forceinline__ void mma16(float* c, const uint32_t* a, const uint32_t* b) {
    asm volatile("mma.sync.aligned.m16n8k16.row.col.f32.f16.f16.f32 "
                 "{%0,%1,%2,%3}, {%4,%5,%6,%7}, {%8,%9}, {%0,%1,%2,%3};"
                 : "+f"(c[0]), "+f"(c[1]), "+f"(c[2]), "+f"(c[3])
                 : "r"(a[0]), "r"(a[1]), "r"(a[2]), "r"(a[3]),
                   "r"(b[0]), "r"(b[1]));
}
__device__ __forceinline__ void ldsm4(uint32_t& r0, uint32_t& r1,
                                      uint32_t& r2, uint32_t& r3, uint32_t addr) {
    asm volatile("ldmatrix.sync.aligned.m8n8.x4.shared.b16 {%0,%1,%2,%3}, [%4];"
                 : "=r"(r0), "=r"(r1), "=r"(r2), "=r"(r3) : "r"(addr));
}

// ------------------------- small kernels -----------------------------------
// Fused fp32 -> fp16 (RN) conversion over up to 5 tensors in one launch.
// Segment table passed by value; block 0 also zeroes g_count.
struct CvtSegs {
    const float4* src[5];
    uint2*        dst[5];
    int           n4[5];      // float4 count per segment
    int           nseg;
};
__global__ void cvt_all_kernel(CvtSegs segs) {
    if (blockIdx.x == 0 && threadIdx.x < NEXP) g_count[threadIdx.x] = 0;
    int stride = gridDim.x * blockDim.x;
    for (int s = 0; s < segs.nseg; ++s) {
        const float4* in = segs.src[s];
        uint2* o = segs.dst[s];
        int n4 = segs.n4[s];
        for (int i = blockIdx.x * blockDim.x + threadIdx.x; i < n4; i += stride) {
            float4 v = in[i];
            __half2 h01 = __floats2half2_rn(v.x, v.y);
            __half2 h23 = __floats2half2_rn(v.z, v.w);
            uint2 u;
            u.x = *(uint32_t*)&h01;
            u.y = *(uint32_t*)&h23;
            o[i] = u;
        }
    }
}

// one warp per token: 8 scores, sigmoid top-2, compact into per-expert lists
__global__ void router_kernel(const float* __restrict__ x,
                              const float* __restrict__ rDE) {
    int warp = (blockIdx.x * blockDim.x + threadIdx.x) >> 5;
    int lane = threadIdx.x & 31;
    if (warp >= TT) return;
    const float* xr = x + (size_t)warp * DDIM;

    float s[8] = {0.f,0.f,0.f,0.f,0.f,0.f,0.f,0.f};
    for (int d = lane; d < DDIM; d += 32) {
        float xv = xr[d];
        const float* rw = rDE + d * 8;
        float4 r0 = *(const float4*)(rw);
        float4 r1 = *(const float4*)(rw + 4);
        s[0] += xv * r0.x;  s[1] += xv * r0.y;
        s[2] += xv * r0.z;  s[3] += xv * r0.w;
        s[4] += xv * r1.x;  s[5] += xv * r1.y;
        s[6] += xv * r1.z;  s[7] += xv * r1.w;
    }
    #pragma unroll
    for (int off = 16; off > 0; off >>= 1) {
        #pragma unroll
        for (int e = 0; e < 8; ++e)
            s[e] += __shfl_xor_sync(0xffffffffu, s[e], off);
    }
    if (lane == 0) {
        int e1 = 0;
        #pragma unroll
        for (int e = 1; e < 8; ++e) if (s[e] > s[e1]) e1 = e;
        int e2 = (e1 == 0) ? 1 : 0;
        #pragma unroll
        for (int e = 0; e < 8; ++e) if (e != e1 && s[e] > s[e2]) e2 = e;
        float g1 = 1.f / (1.f + expf(-s[e1]));
        float g2 = 1.f / (1.f + expf(-s[e2]));
        int p1 = atomicAdd(&g_count[e1], 1);
        g_tok_list [e1 * TT + p1] = warp;
        g_gate_list[e1 * TT + p1] = g1;
        int p2 = atomicAdd(&g_count[e2], 1);
        g_tok_list [e2 * TT + p2] = warp;
        g_gate_list[e2 * TT + p2] = g2;
    }
}

// single block: padded prefix offsets, row-block->expert map, compacted arrays
__global__ void build_offsets_kernel() {
    __shared__ int sOff[NEXP];
    __shared__ int sCnt[NEXP];
    int tid = threadIdx.x;
    if (tid == 0) {
        int po = 0;
        for (int e = 0; e < NEXP; ++e) {
            int c = g_count[e];
            sCnt[e] = c;
            sOff[e] = po;
            int nrb = (c + 127) >> 7;
            for (int r = 0; r < nrb; ++r) g_rb_expert[(po >> 7) + r] = e;
            po += nrb << 7;
        }
        for (int rb = po >> 7; rb < NRB; ++rb) g_rb_expert[rb] = -1;
    }
    __syncthreads();
    for (int i = tid; i < NPAD; i += blockDim.x) {
        g_comp_tok[i]  = 0;
        g_comp_gate[i] = 0.f;
    }
    __syncthreads();
    for (int e = 0; e < NEXP; ++e) {
        int c = sCnt[e], o = sOff[e];
        for (int i = tid; i < c; i += blockDim.x) {
            g_comp_tok [o + i] = g_tok_list [e * TT + i];
            g_comp_gate[o + i] = g_gate_list[e * TT + i];
        }
    }
}

// materialize gated gathered token matrix (NPAD x D), fp16
__global__ void gather_scale_kernel(const float* __restrict__ x) {
    int row = blockIdx.x;
    int tok = g_comp_tok[row];
    float g  = g_comp_gate[row];
    const float4* src = (const float4*)(x + (size_t)tok * DDIM);
    uint2* dst = (uint2*)(g_gathA + (size_t)row * DDIM);
    for (int i = threadIdx.x; i < DDIM / 4; i += blockDim.x) {
        float4 v = src[i];
        __half2 h01 = __floats2half2_rn(v.x * g, v.y * g);
        __half2 h23 = __floats2half2_rn(v.z * g, v.w * g);
        uint2 u;
        u.x = *(uint32_t*)&h01;
        u.y = *(uint32_t*)&h23;
        dst[i] = u;
    }
}

// ---------------------------------------------------------------------------
// fp16 mma.sync GEMM (m16n8k16), ldmatrix x4, 4 warps (2x2), warp tile 64x64,
// block tile 128 rows x 128 B-rows, K-chunk 64 (4 k16 steps), 3-stage depth-2
// cp.async pipeline, 128 threads, 2 CTAs/SM. fp32 accumulation.
//   FUSE=1: B rows interleave w1/w3; epilogue stores act = half(silu(g)*u).
//   FUSE=0, EPI=0: float2 stores to float C (ld = N)
//   FUSE=0, EPI=1: atomicAdd into float C[rowTok[row]*N + col]
//   rbExpert != null: per-row-block expert weight base (skip blocks with -1)
// ---------------------------------------------------------------------------
template<int FUSE, int EPI>
__global__ void __launch_bounds__(128, 2)
mma_gemm_kernel(const __half* __restrict__ A, const __half* __restrict__ W,
                void* __restrict__ Cv, int N,
                const int* __restrict__ rbExpert, size_t wStride,
                const int* __restrict__ rowTok)
{
    extern __shared__ __half sm[];
    const int rowBase = blockIdx.y * 128;
    const int colBase = blockIdx.x * 128;

    const __half* Wb = W;
    if (rbExpert) {
        int e = rbExpert[blockIdx.y];
        if (e < 0) return;                 // fully-padded row block
        Wb += (size_t)e * wStride;
    }

    const int tid = threadIdx.x;
    const int wid = tid >> 5, lid = tid & 31;
    const int g = lid >> 2, tg = lid & 3;
    const int warpM = wid >> 1, warpN = wid & 1;

    const uint32_t smu = smem_u32(sm);

    auto load_stage = [&](int c, int st) {
        uint32_t base = smu + (uint32_t)st * (STG_H * 2);
        const __half* aG = A + (size_t)rowBase * 2048 + c * 64;
        #pragma unroll
        for (int s = 0; s < 8; ++s) {      // A: 128 rows x 8 16B segs
            int i = tid + s * 128, r = i >> 3, q = i & 7;
            cp16(base + (uint32_t)(r * SROW_H + q * 8) * 2,
                 aG + (size_t)r * 2048 + q * 8);
        }
        #pragma unroll
        for (int s = 0; s < 8; ++s) {      // B: 128 rows x 8 16B segs
            int i = tid + s * 128, r = i >> 3, q = i & 7;
            const __half* bsrc;
            if (FUSE) {
                bsrc = Wb + (size_t)((r & 1) * FDIM + (colBase >> 1) + (r >> 1)) * 2048
                          + c * 64 + q * 8;
            } else {
                bsrc = Wb + (size_t)(colBase + r) * 2048 + c * 64 + q * 8;
            }
            cp16(base + (uint32_t)(ASTG_H + r * SROW_H + q * 8) * 2, bsrc);
        }
        asm volatile("cp.async.commit_group;" ::: "memory");
    };

    load_stage(0, 0);
    load_stage(1, 1);

    float acc[4][8][4];
    #pragma unroll
    for (int mf = 0; mf < 4; ++mf)
        #pragma unroll
        for (int nf = 0; nf < 8; ++nf)
            #pragma unroll
            for (int j = 0; j < 4; ++j) acc[mf][nf][j] = 0.f;

    const uint32_t aThrOff =
        (uint32_t)(((warpM * 64 + (lid & 15)) * SROW_H + (lid >> 4) * 8) * 2);
    const uint32_t bThrOff =
        (uint32_t)((ASTG_H + (warpN * 64 + (lid & 15)) * SROW_H + (lid >> 4) * 8) * 2);

    for (int ck = 0; ck < NC; ++ck) {
        if (ck < NC - 2)       asm volatile("cp.async.wait_group 1;" ::: "memory");
        else                   asm volatile("cp.async.wait_group 0;" ::: "memory");
        __syncthreads();
        if (ck + 2 < NC) load_stage(ck + 2, (ck + 2) % NSTAGE);

        const uint32_t stB = smu + (uint32_t)(ck % NSTAGE) * (STG_H * 2);
        const uint32_t aB = stB + aThrOff;
        const uint32_t bB = stB + bThrOff;

        #pragma unroll
        for (int ks = 0; ks < 4; ++ks) {           // four k16 steps per chunk
            const uint32_t kByte = (uint32_t)(ks * 32);
            uint32_t a[4][4], b[8][2];
            #pragma unroll
            for (int mf = 0; mf < 4; ++mf)
                ldsm4(a[mf][0], a[mf][1], a[mf][2], a[mf][3],
                      aB + (uint32_t)(mf * 16 * SROW_H * 2) + kByte);
            #pragma unroll
            for (int j = 0; j < 4; ++j)
                ldsm4(b[2*j][0], b[2*j+1][0], b[2*j][1], b[2*j+1][1],
                      bB + (uint32_t)(j * 16 * SROW_H * 2) + kByte);
            #pragma unroll
            for (int mf = 0; mf < 4; ++mf)
                #pragma unroll
                for (int nf = 0; nf < 8; ++nf)
                    mma16(acc[mf][nf], a[mf], b[nf]);
        }
    }

    // epilogue
    const int rW = rowBase + warpM * 64;
    #pragma unroll
    for (int mf = 0; mf < 4; ++mf) {
        int r0 = rW + mf * 16 + g;
        int r1 = r0 + 8;
        if (FUSE) {
            __half* C = (__half*)Cv;
            #pragma unroll
            for (int nf = 0; nf < 8; ++nf) {
                int acol = (colBase >> 1) + warpN * 32 + nf * 4 + tg;
                float g0 = acc[mf][nf][0], u0 = acc[mf][nf][1];
                float g1 = acc[mf][nf][2], u1 = acc[mf][nf][3];
                C[(size_t)r0 * N + acol] =
                    __float2half_rn(g0 / (1.f + __expf(-g0)) * u0);
                C[(size_t)r1 * N + acol] =
                    __float2half_rn(g1 / (1.f + __expf(-g1)) * u1);
            }
        } else if (EPI == 0) {
            float* C = (float*)Cv;
            const int cW = colBase + warpN * 64;
            #pragma unroll
            for (int nf = 0; nf < 8; ++nf) {
                int col = cW + nf * 8 + tg * 2;
                *(float2*)(C + (size_t)r0 * N + col) =
                    make_float2(acc[mf][nf][0], acc[mf][nf][1]);
                *(float2*)(C + (size_t)r1 * N + col) =
                    make_float2(acc[mf][nf][2], acc[mf][nf][3]);
            }
        } else {
            float* C = (float*)Cv;
            const int cW = colBase + warpN * 64;
            int t0 = rowTok[r0];
            int t1 = rowTok[r1];
            #pragma unroll
            for (int nf = 0; nf < 8; ++nf) {
                int col = cW + nf * 8 + tg * 2;
                float* o0 = C + (size_t)t0 * N + col;
                float* o1 = C + (size_t)t1 * N + col;
                atomicAdd(o0 + 0, acc[mf][nf][0]);
                atomicAdd(o0 + 1, acc[mf][nf][1]);
                atomicAdd(o1 + 0, acc[mf][nf][2]);
                atomicAdd(o1 + 1, acc[mf][nf][3]);
            }
        }
    }
}

// ---------------------------------------------------------------------------
extern "C" void kernel_launch(void* const* d_in, const int* in_sizes, int n_in,
                              void* d_out, int out_size) {
    (void)in_sizes; (void)n_in; (void)out_size;
    const float* x    = (const float*)d_in[0];
    const float* rDE  = (const float*)d_in[1];
    const float* sw13 = (const float*)d_in[2];
    const float* sw2  = (const float*)d_in[3];
    const float* rw13 = (const float*)d_in[4];
    const float* rw2  = (const float*)d_in[5];
    float* out = (float*)d_out;

    __half *p_sact, *p_ract, *p_gathA, *p_xh, *p_w13h, *p_w2h, *p_rw13h, *p_rw2h;
    int *p_ctok, *p_rbe;
    cudaGetSymbolAddress((void**)&p_sact,  g_shared_act);
    cudaGetSymbolAddress((void**)&p_ract,  g_rout_act);
    cudaGetSymbolAddress((void**)&p_gathA, g_gathA);
    cudaGetSymbolAddress((void**)&p_xh,    g_xh);
    cudaGetSymbolAddress((void**)&p_w13h,  g_w13h);
    cudaGetSymbolAddress((void**)&p_w2h,   g_w2h);
    cudaGetSymbolAddress((void**)&p_rw13h, g_rw13h);
    cudaGetSymbolAddress((void**)&p_rw2h,  g_rw2h);
    cudaGetSymbolAddress((void**)&p_ctok,  g_comp_tok);
    cudaGetSymbolAddress((void**)&p_rbe,   g_rb_expert);

    cudaFuncSetAttribute(mma_gemm_kernel<1, 0>,
                         cudaFuncAttributeMaxDynamicSharedMemorySize, SMEM_BYTES);
    cudaFuncSetAttribute(mma_gemm_kernel<0, 0>,
                         cudaFuncAttributeMaxDynamicSharedMemorySize, SMEM_BYTES);
    cudaFuncSetAttribute(mma_gemm_kernel<0, 1>,
                         cudaFuncAttributeMaxDynamicSharedMemorySize, SMEM_BYTES);

    // 1) fused conversions (+ zero counts inside, block 0)
    CvtSegs segs;
    segs.src[0] = (const float4*)x;    segs.dst[0] = (uint2*)p_xh;    segs.n4[0] = TT * DDIM / 4;
    segs.src[1] = (const float4*)sw13; segs.dst[1] = (uint2*)p_w13h;  segs.n4[1] = TWO_F * DDIM / 4;
    segs.src[2] = (const float4*)sw2;  segs.dst[2] = (uint2*)p_w2h;   segs.n4[2] = DDIM * FDIM / 4;
    segs.src[3] = (const float4*)rw13; segs.dst[3] = (uint2*)p_rw13h; segs.n4[3] = NEXP * TWO_F * DDIM / 4;
    segs.src[4] = (const float4*)rw2;  segs.dst[4] = (uint2*)p_rw2h;  segs.n4[4] = NEXP * DDIM * FDIM / 4;
    segs.nseg = 5;
    cvt_all_kernel<<<4736, 256>>>(segs);                                   // 1

    router_kernel<<<TT / 8, 256>>>(x, rDE);                                // 2
    build_offsets_kernel<<<1, 256>>>();                                    // 3
    gather_scale_kernel<<<NPAD, 256>>>(x);                                 // 4

    // shared expert GEMM1 + fused swiglu: act = swiglu(x @ w13^T)         // 5
    mma_gemm_kernel<1, 0><<<dim3(TWO_F / 128, TT / 128), 128, SMEM_BYTES>>>(
        p_xh, p_w13h, p_sact, FDIM, nullptr, 0, nullptr);
    // shared expert GEMM2: out = act @ w2^T  (writes every output element) // 6
    mma_gemm_kernel<0, 0><<<dim3(DDIM / 128, TT / 128), 128, SMEM_BYTES>>>(
        p_sact, p_w2h, out, DDIM, nullptr, 0, nullptr);
    // routed GEMM1 + fused swiglu: act = swiglu(gathA @ w13_e^T)          // 7
    mma_gemm_kernel<1, 0><<<dim3(TWO_F / 128, NRB), 128, SMEM_BYTES>>>(
        p_gathA, p_rw13h, p_ract, FDIM, p_rbe, (size_t)TWO_F * DDIM, nullptr);
    // routed GEMM2: out[tok] += act @ w2_e^T  (atomic scatter)            // 8
    mma_gemm_kernel<0, 1><<<dim3(DDIM / 128, NRB), 128, SMEM_BYTES>>>(
        p_ract, p_rw2h, out, DDIM, p_rbe, (size_t)DDIM * FDIM, p_ctok);
}

// round 14
// speedup vs baseline: 1.0414x; 1.0414x over previous
#include <cuda_runtime.h>
#include <cuda_fp16.h>
#include <math.h>
#include <stdint.h>

// ---------------------------------------------------------------------------
// Problem constants: B=2, T=2048 -> Tt=4096 tokens, D=2048, F=2048, E=8, K=2
// All four GEMMs share K = 2048.
// ---------------------------------------------------------------------------
#define TT      4096
#define DDIM    2048
#define FDIM    2048
#define TWO_F   4096
#define NEXP    8
#define NPAD    9216          // 72 row-blocks of 128 (8192 assignments + padding)
#define NRB     72

#define NC      32            // K chunks (2048 / 64)
#define SROW_H  72            // padded smem row stride (halves): 144B/row
#define ASTG_H  (128 * SROW_H)   // A stage halves (128 rows)
#define BSTG_H  (128 * SROW_H)   // B stage halves (128 rows)
#define STG_H   (ASTG_H + BSTG_H)
#define NSTAGE  3
#define SMEM_BYTES (NSTAGE * STG_H * 2)   // 110592 -> 2 CTAs/SM

// ------------------------- device scratch (no cudaMalloc allowed) ----------
__device__ __half g_shared_act[(size_t)TT * FDIM];       // 16 MB
__device__ __half g_rout_act  [(size_t)NPAD * FDIM];     // 36 MB
__device__ __half g_xh        [(size_t)TT * DDIM];       // 16 MB (fp16 x)
__device__ __half g_w13h      [(size_t)TWO_F * DDIM];    // 16 MB
__device__ __half g_w2h       [(size_t)DDIM * FDIM];     // 8 MB
__device__ __half g_rw13h     [(size_t)NEXP * TWO_F * DDIM];  // 128 MB
__device__ __half g_rw2h      [(size_t)NEXP * DDIM * FDIM];   // 64 MB
__device__ int    g_count[NEXP];
__device__ int    g_tok_list [NEXP * TT];
__device__ float  g_gate_list[NEXP * TT];
__device__ int    g_comp_tok [NPAD];
__device__ float  g_comp_gate[NPAD];
__device__ int    g_rb_expert[NRB];

// ------------------------- helpers -----------------------------------------
__device__ __forceinline__ uint32_t smem_u32(const void* p) {
    uint32_t a;
    asm("{ .reg .u64 t; cvta.to.shared.u64 t, %1; cvt.u32.u64 %0, t; }"
        : "=r"(a) : "l"(p));
    return a;
}
__device__ __forceinline__ void cp16(uint32_t dst, const void* src) {
    asm volatile("cp.async.cg.shared.global [%0], [%1], 16;" :: "r"(dst), "l"(src));
}
__device__ __forceinline__ void mma16(float* c, const uint32_t* a, const uint32_t* b) {
    asm volatile("mma.sync.aligned.m16n8k16.row.col.f32.f16.f16.f32 "
                 "{%0,%1,%2,%3}, {%4,%5,%6,%7}, {%8,%9}, {%0,%1,%2,%3};"
                 : "+f"(c[0]), "+f"(c[1]), "+f"(c[2]), "+f"(c[3])
                 : "r"(a[0]), "r"(a[1]), "r"(a[2]), "r"(a[3]),
                   "r"(b[0]), "r"(b[1]));
}
__device__ __forceinline__ void ldsm4(uint32_t& r0, uint32_t& r1,
                                      uint32_t& r2, uint32_t& r3, uint32_t addr) {
    asm volatile("ldmatrix.sync.aligned.m8n8.x4.shared.b16 {%0,%1,%2,%3}, [%4];"
                 : "=r"(r0), "=r"(r1), "=r"(r2), "=r"(r3) : "r"(addr));
}

// ------------------------- small kernels -----------------------------------
__global__ void zero_counts_kernel() {
    if (threadIdx.x < NEXP) g_count[threadIdx.x] = 0;
}

// fp32 -> fp16 (RN) conversion
__global__ void cvt_half_kernel(const float4* __restrict__ in,
                                uint2* __restrict__ o, int n4) {
    int stride = gridDim.x * blockDim.x;
    for (int i = blockIdx.x * blockDim.x + threadIdx.x; i < n4; i += stride) {
        float4 v = in[i];
        __half2 h01 = __floats2half2_rn(v.x, v.y);
        __half2 h23 = __floats2half2_rn(v.z, v.w);
        uint2 u;
        u.x = *(uint32_t*)&h01;
        u.y = *(uint32_t*)&h23;
        o[i] = u;
    }
}

// one warp per token: 8 scores, sigmoid top-2, compact into per-expert lists
__global__ void router_kernel(const float* __restrict__ x,
                              const float* __restrict__ rDE) {
    int warp = (blockIdx.x * blockDim.x + threadIdx.x) >> 5;
    int lane = threadIdx.x & 31;
    if (warp >= TT) return;
    const float* xr = x + (size_t)warp * DDIM;

    float s[8] = {0.f,0.f,0.f,0.f,0.f,0.f,0.f,0.f};
    for (int d = lane; d < DDIM; d += 32) {
        float xv = xr[d];
        const float* rw = rDE + d * 8;
        float4 r0 = *(const float4*)(rw);
        float4 r1 = *(const float4*)(rw + 4);
        s[0] += xv * r0.x;  s[1] += xv * r0.y;
        s[2] += xv * r0.z;  s[3] += xv * r0.w;
        s[4] += xv * r1.x;  s[5] += xv * r1.y;
        s[6] += xv * r1.z;  s[7] += xv * r1.w;
    }
    #pragma unroll
    for (int off = 16; off > 0; off >>= 1) {
        #pragma unroll
        for (int e = 0; e < 8; ++e)
            s[e] += __shfl_xor_sync(0xffffffffu, s[e], off);
    }
    if (lane == 0) {
        int e1 = 0;
        #pragma unroll
        for (int e = 1; e < 8; ++e) if (s[e] > s[e1]) e1 = e;
        int e2 = (e1 == 0) ? 1 : 0;
        #pragma unroll
        for (int e = 0; e < 8; ++e) if (e != e1 && s[e] > s[e2]) e2 = e;
        float g1 = 1.f / (1.f + expf(-s[e1]));
        float g2 = 1.f / (1.f + expf(-s[e2]));
        int p1 = atomicAdd(&g_count[e1], 1);
        g_tok_list [e1 * TT + p1] = warp;
        g_gate_list[e1 * TT + p1] = g1;
        int p2 = atomicAdd(&g_count[e2], 1);
        g_tok_list [e2 * TT + p2] = warp;
        g_gate_list[e2 * TT + p2] = g2;
    }
}

// single block: padded prefix offsets, row-block->expert map, compacted arrays
__global__ void build_offsets_kernel() {
    __shared__ int sOff[NEXP];
    __shared__ int sCnt[NEXP];
    int tid = threadIdx.x;
    if (tid == 0) {
        int po = 0;
        for (int e = 0; e < NEXP; ++e) {
            int c = g_count[e];
            sCnt[e] = c;
            sOff[e] = po;
            int nrb = (c + 127) >> 7;
            for (int r = 0; r < nrb; ++r) g_rb_expert[(po >> 7) + r] = e;
            po += nrb << 7;
        }
        for (int rb = po >> 7; rb < NRB; ++rb) g_rb_expert[rb] = -1;
    }
    __syncthreads();
    for (int i = tid; i < NPAD; i += blockDim.x) {
        g_comp_tok[i]  = 0;
        g_comp_gate[i] = 0.f;
    }
    __syncthreads();
    for (int e = 0; e < NEXP; ++e) {
        int c = sCnt[e], o = sOff[e];
        for (int i = tid; i < c; i += blockDim.x) {
            g_comp_tok [o + i] = g_tok_list [e * TT + i];
            g_comp_gate[o + i] = g_gate_list[e * TT + i];
        }
    }
}

// ---------------------------------------------------------------------------
// fp16 mma.sync GEMM (m16n8k16), ldmatrix x4, 4 warps (2x2), warp tile 64x64,
// block tile 128 rows x 128 B-rows, K-chunk 64 (4 k16 steps), 3-stage depth-2
// cp.async pipeline, 128 threads, 2 CTAs/SM. fp32 accumulation.
//   GATHER=1: A rows gathered via rowTok (un-gated fp16 tokens); the per-row
//             gate is applied in the fp32 epilogue: act = silu(g*y0)*(g*y1).
//             ((g*x)@W == g*(x@W): GEMM is linear in x, swiglu is not — gate
//             must scale both halves BEFORE swiglu, which the epilogue does.)
//   FUSE=1: B rows interleave w1/w3; epilogue stores act = half(...).
//   FUSE=0, EPI=0: float2 stores to float C (ld = N)
//   FUSE=0, EPI=1: atomicAdd into float C[rowTok[row]*N + col]
//   rbExpert != null: per-row-block expert weight base (skip blocks with -1)
// ---------------------------------------------------------------------------
template<int FUSE, int EPI, int GATHER>
__global__ void __launch_bounds__(128, 2)
mma_gemm_kernel(const __half* __restrict__ A, const __half* __restrict__ W,
                void* __restrict__ Cv, int N,
                const int* __restrict__ rbExpert, size_t wStride,
                const int* __restrict__ rowTok,
                const float* __restrict__ rowGate)
{
    extern __shared__ __half sm[];
    __shared__ int sTok[128];
    const int rowBase = blockIdx.y * 128;
    const int colBase = blockIdx.x * 128;

    const __half* Wb = W;
    if (rbExpert) {
        int e = rbExpert[blockIdx.y];
        if (e < 0) return;                 // fully-padded row block
        Wb += (size_t)e * wStride;
    }

    const int tid = threadIdx.x;
    const int wid = tid >> 5, lid = tid & 31;
    const int g = lid >> 2, tg = lid & 3;
    const int warpM = wid >> 1, warpN = wid & 1;

    if (GATHER) {
        sTok[tid] = rowTok[rowBase + tid];   // 128 threads, one row each
        __syncthreads();
    }

    const uint32_t smu = smem_u32(sm);

    auto load_stage = [&](int c, int st) {
        uint32_t base = smu + (uint32_t)st * (STG_H * 2);
        #pragma unroll
        for (int s = 0; s < 8; ++s) {      // A: 128 rows x 8 16B segs
            int i = tid + s * 128, r = i >> 3, q = i & 7;
            const __half* asrc;
            if (GATHER) asrc = A + (size_t)sTok[r] * 2048 + c * 64 + q * 8;
            else        asrc = A + (size_t)(rowBase + r) * 2048 + c * 64 + q * 8;
            cp16(base + (uint32_t)(r * SROW_H + q * 8) * 2, asrc);
        }
        #pragma unroll
        for (int s = 0; s < 8; ++s) {      // B: 128 rows x 8 16B segs
            int i = tid + s * 128, r = i >> 3, q = i & 7;
            const __half* bsrc;
            if (FUSE) {
                bsrc = Wb + (size_t)((r & 1) * FDIM + (colBase >> 1) + (r >> 1)) * 2048
                          + c * 64 + q * 8;
            } else {
                bsrc = Wb + (size_t)(colBase + r) * 2048 + c * 64 + q * 8;
            }
            cp16(base + (uint32_t)(ASTG_H + r * SROW_H + q * 8) * 2, bsrc);
        }
        asm volatile("cp.async.commit_group;" ::: "memory");
    };

    load_stage(0, 0);
    load_stage(1, 1);

    float acc[4][8][4];
    #pragma unroll
    for (int mf = 0; mf < 4; ++mf)
        #pragma unroll
        for (int nf = 0; nf < 8; ++nf)
            #pragma unroll
            for (int j = 0; j < 4; ++j) acc[mf][nf][j] = 0.f;

    const uint32_t aThrOff =
        (uint32_t)(((warpM * 64 + (lid & 15)) * SROW_H + (lid >> 4) * 8) * 2);
    const uint32_t bThrOff =
        (uint32_t)((ASTG_H + (warpN * 64 + (lid & 15)) * SROW_H + (lid >> 4) * 8) * 2);

    for (int ck = 0; ck < NC; ++ck) {
        if (ck < NC - 2)       asm volatile("cp.async.wait_group 1;" ::: "memory");
        else                   asm volatile("cp.async.wait_group 0;" ::: "memory");
        __syncthreads();
        if (ck + 2 < NC) load_stage(ck + 2, (ck + 2) % NSTAGE);

        const uint32_t stB = smu + (uint32_t)(ck % NSTAGE) * (STG_H * 2);
        const uint32_t aB = stB + aThrOff;
        const uint32_t bB = stB + bThrOff;

        #pragma unroll
        for (int ks = 0; ks < 4; ++ks) {           // four k16 steps per chunk
            const uint32_t kByte = (uint32_t)(ks * 32);
            uint32_t a[4][4], b[8][2];
            #pragma unroll
            for (int mf = 0; mf < 4; ++mf)
                ldsm4(a[mf][0], a[mf][1], a[mf][2], a[mf][3],
                      aB + (uint32_t)(mf * 16 * SROW_H * 2) + kByte);
            #pragma unroll
            for (int j = 0; j < 4; ++j)
                ldsm4(b[2*j][0], b[2*j+1][0], b[2*j][1], b[2*j+1][1],
                      bB + (uint32_t)(j * 16 * SROW_H * 2) + kByte);
            #pragma unroll
            for (int mf = 0; mf < 4; ++mf)
                #pragma unroll
                for (int nf = 0; nf < 8; ++nf)
                    mma16(acc[mf][nf], a[mf], b[nf]);
        }
    }

    // epilogue
    const int rW = rowBase + warpM * 64;
    #pragma unroll
    for (int mf = 0; mf < 4; ++mf) {
        int r0 = rW + mf * 16 + g;
        int r1 = r0 + 8;
        if (FUSE) {
            __half* C = (__half*)Cv;
            float gt0 = 1.f, gt1 = 1.f;
            if (GATHER) { gt0 = rowGate[r0]; gt1 = rowGate[r1]; }
            #pragma unroll
            for (int nf = 0; nf < 8; ++nf) {
                int acol = (colBase >> 1) + warpN * 32 + nf * 4 + tg;
                float g0 = acc[mf][nf][0] * gt0, u0 = acc[mf][nf][1] * gt0;
                float g1 = acc[mf][nf][2] * gt1, u1 = acc[mf][nf][3] * gt1;
                C[(size_t)r0 * N + acol] =
                    __float2half_rn(g0 / (1.f + __expf(-g0)) * u0);
                C[(size_t)r1 * N + acol] =
                    __float2half_rn(g1 / (1.f + __expf(-g1)) * u1);
            }
        } else if (EPI == 0) {
            float* C = (float*)Cv;
            const int cW = colBase + warpN * 64;
            #pragma unroll
            for (int nf = 0; nf < 8; ++nf) {
                int col = cW + nf * 8 + tg * 2;
                *(float2*)(C + (size_t)r0 * N + col) =
                    make_float2(acc[mf][nf][0], acc[mf][nf][1]);
                *(float2*)(C + (size_t)r1 * N + col) =
                    make_float2(acc[mf][nf][2], acc[mf][nf][3]);
            }
        } else {
            float* C = (float*)Cv;
            const int cW = colBase + warpN * 64;
            int t0 = rowTok[r0];
            int t1 = rowTok[r1];
            #pragma unroll
            for (int nf = 0; nf < 8; ++nf) {
                int col = cW + nf * 8 + tg * 2;
                float* o0 = C + (size_t)t0 * N + col;
                float* o1 = C + (size_t)t1 * N + col;
                atomicAdd(o0 + 0, acc[mf][nf][0]);
                atomicAdd(o0 + 1, acc[mf][nf][1]);
                atomicAdd(o1 + 0, acc[mf][nf][2]);
                atomicAdd(o1 + 1, acc[mf][nf][3]);
            }
        }
    }
}

// ---------------------------------------------------------------------------
extern "C" void kernel_launch(void* const* d_in, const int* in_sizes, int n_in,
                              void* d_out, int out_size) {
    (void)in_sizes; (void)n_in; (void)out_size;
    const float* x    = (const float*)d_in[0];
    const float* rDE  = (const float*)d_in[1];
    const float* sw13 = (const float*)d_in[2];
    const float* sw2  = (const float*)d_in[3];
    const float* rw13 = (const float*)d_in[4];
    const float* rw2  = (const float*)d_in[5];
    float* out = (float*)d_out;

    __half *p_sact, *p_ract, *p_xh, *p_w13h, *p_w2h, *p_rw13h, *p_rw2h;
    int *p_ctok, *p_rbe;
    float *p_cgate;
    cudaGetSymbolAddress((void**)&p_sact,  g_shared_act);
    cudaGetSymbolAddress((void**)&p_ract,  g_rout_act);
    cudaGetSymbolAddress((void**)&p_xh,    g_xh);
    cudaGetSymbolAddress((void**)&p_w13h,  g_w13h);
    cudaGetSymbolAddress((void**)&p_w2h,   g_w2h);
    cudaGetSymbolAddress((void**)&p_rw13h, g_rw13h);
    cudaGetSymbolAddress((void**)&p_rw2h,  g_rw2h);
    cudaGetSymbolAddress((void**)&p_ctok,  g_comp_tok);
    cudaGetSymbolAddress((void**)&p_cgate, g_comp_gate);
    cudaGetSymbolAddress((void**)&p_rbe,   g_rb_expert);

    cudaFuncSetAttribute(mma_gemm_kernel<1, 0, 0>,
                         cudaFuncAttributeMaxDynamicSharedMemorySize, SMEM_BYTES);
    cudaFuncSetAttribute(mma_gemm_kernel<1, 0, 1>,
                         cudaFuncAttributeMaxDynamicSharedMemorySize, SMEM_BYTES);
    cudaFuncSetAttribute(mma_gemm_kernel<0, 0, 0>,
                         cudaFuncAttributeMaxDynamicSharedMemorySize, SMEM_BYTES);
    cudaFuncSetAttribute(mma_gemm_kernel<0, 1, 0>,
                         cudaFuncAttributeMaxDynamicSharedMemorySize, SMEM_BYTES);

    // R9-proven serial launch structure (separate cvt kernels; no streams)
    cvt_half_kernel<<<2048, 256>>>((const float4*)x,    (uint2*)p_xh,   TT * DDIM / 4);
    cvt_half_kernel<<<2048, 256>>>((const float4*)sw13, (uint2*)p_w13h, TWO_F * DDIM / 4);
    cvt_half_kernel<<<2048, 256>>>((const float4*)sw2,  (uint2*)p_w2h,  DDIM * FDIM / 4);
    zero_counts_kernel<<<1, 32>>>();
    // shared expert GEMM1 + fused swiglu: act = swiglu(x @ w13^T)
    mma_gemm_kernel<1, 0, 0><<<dim3(TWO_F / 128, TT / 128), 128, SMEM_BYTES>>>(
        p_xh, p_w13h, p_sact, FDIM, nullptr, 0, nullptr, nullptr);
    // shared expert GEMM2: out = act @ w2^T  (writes every output element)
    mma_gemm_kernel<0, 0, 0><<<dim3(DDIM / 128, TT / 128), 128, SMEM_BYTES>>>(
        p_sact, p_w2h, out, DDIM, nullptr, 0, nullptr, nullptr);

    router_kernel<<<TT / 8, 256>>>(x, rDE);
    build_offsets_kernel<<<1, 256>>>();
    cvt_half_kernel<<<4096, 256>>>((const float4*)rw13, (uint2*)p_rw13h, NEXP * TWO_F * DDIM / 4);
    cvt_half_kernel<<<4096, 256>>>((const float4*)rw2,  (uint2*)p_rw2h,  NEXP * DDIM * FDIM / 4);

    // routed GEMM1 + fused swiglu, gathering rows of xh directly (gate applied
    // in the fp32 epilogue): act = swiglu(g * (x[tok] @ w13_e^T))
    mma_gemm_kernel<1, 0, 1><<<dim3(TWO_F / 128, NRB), 128, SMEM_BYTES>>>(
        p_xh, p_rw13h, p_ract, FDIM, p_rbe, (size_t)TWO_F * DDIM, p_ctok, p_cgate);
    // routed GEMM2: out[tok] += act @ w2_e^T  (atomic scatter)
    mma_gemm_kernel<0, 1, 0><<<dim3(DDIM / 128, NRB), 128, SMEM_BYTES>>>(
        p_ract, p_rw2h, out, DDIM, p_rbe, (size_t)DDIM * FDIM, p_ctok, nullptr);
}

// round 15
// speedup vs baseline: 1.5220x; 1.4615x over previous
#include <cuda_runtime.h>
#include <cuda_fp16.h>
#include <math.h>
#include <stdint.h>

// ---------------------------------------------------------------------------
// Problem constants: B=2, T=2048 -> Tt=4096 tokens, D=2048, F=2048, E=8, K=2
// All four GEMMs share K = 2048.
// ---------------------------------------------------------------------------
#define TT      4096
#define DDIM    2048
#define FDIM    2048
#define TWO_F   4096
#define NEXP    8
#define NPAD    9216          // 72 row-blocks of 128 (8192 assignments + padding)
#define NRB     72

#define NC      32            // K chunks (2048 / 64)
#define SROW_H  72            // padded smem row stride (halves): 144B/row
#define ASTG_H  (128 * SROW_H)   // A stage halves (128 rows)
#define BSTG_H  (128 * SROW_H)   // B stage halves (128 rows)
#define STG_H   (ASTG_H + BSTG_H)
#define NSTAGE  3
#define SMEM_BYTES (NSTAGE * STG_H * 2)   // 110592 -> 2 CTAs/SM

// ------------------------- device scratch (no cudaMalloc allowed) ----------
__device__ __half g_shared_act[(size_t)TT * FDIM];       // 16 MB
__device__ __half g_rout_act  [(size_t)NPAD * FDIM];     // 36 MB
__device__ __half g_gathA     [(size_t)NPAD * DDIM];     // 36 MB
__device__ __half g_xh        [(size_t)TT * DDIM];       // 16 MB (fp16 x)
__device__ __half g_w13h      [(size_t)TWO_F * DDIM];    // 16 MB
__device__ __half g_w2h       [(size_t)DDIM * FDIM];     // 8 MB
__device__ __half g_rw13h     [(size_t)NEXP * TWO_F * DDIM];  // 128 MB
__device__ __half g_rw2h      [(size_t)NEXP * DDIM * FDIM];   // 64 MB
__device__ int    g_count[NEXP];
__device__ int    g_tok_list [NEXP * TT];
__device__ float  g_gate_list[NEXP * TT];
__device__ int    g_comp_tok [NPAD];
__device__ float  g_comp_gate[NPAD];
__device__ int    g_rb_expert[NRB];

// ------------------------- helpers -----------------------------------------
__device__ __forceinline__ uint32_t smem_u32(const void* p) {
    uint32_t a;
    asm("{ .reg .u64 t; cvta.to.shared.u64 t, %1; cvt.u32.u64 %0, t; }"
        : "=r"(a) : "l"(p));
    return a;
}
__device__ __forceinline__ void cp16(uint32_t dst, const void* src) {
    asm volatile("cp.async.cg.shared.global [%0], [%1], 16;" :: "r"(dst), "l"(src));
}
__device__ __forceinline__ void mma16(float* c, const uint32_t* a, const uint32_t* b) {
    asm volatile("mma.sync.aligned.m16n8k16.row.col.f32.f16.f16.f32 "
                 "{%0,%1,%2,%3}, {%4,%5,%6,%7}, {%8,%9}, {%0,%1,%2,%3};"
                 : "+f"(c[0]), "+f"(c[1]), "+f"(c[2]), "+f"(c[3])
                 : "r"(a[0]), "r"(a[1]), "r"(a[2]), "r"(a[3]),
                   "r"(b[0]), "r"(b[1]));
}
__device__ __forceinline__ void ldsm4(uint32_t& r0, uint32_t& r1,
                                      uint32_t& r2, uint32_t& r3, uint32_t addr) {
    asm volatile("ldmatrix.sync.aligned.m8n8.x4.shared.b16 {%0,%1,%2,%3}, [%4];"
                 : "=r"(r0), "=r"(r1), "=r"(r2), "=r"(r3) : "r"(addr));
}

// ------------------------- small kernels -----------------------------------
// fp32 -> fp16 (RN) conversion. ZERO=1: block 0 also clears g_count.
template<int ZERO>
__global__ void cvt_half_kernel(const float4* __restrict__ in,
                                uint2* __restrict__ o, int n4) {
    if (ZERO && blockIdx.x == 0 && threadIdx.x < NEXP) g_count[threadIdx.x] = 0;
    int stride = gridDim.x * blockDim.x;
    for (int i = blockIdx.x * blockDim.x + threadIdx.x; i < n4; i += stride) {
        float4 v = in[i];
        __half2 h01 = __floats2half2_rn(v.x, v.y);
        __half2 h23 = __floats2half2_rn(v.z, v.w);
        uint2 u;
        u.x = *(uint32_t*)&h01;
        u.y = *(uint32_t*)&h23;
        o[i] = u;
    }
}

// one warp per token: 8 scores, sigmoid top-2, compact into per-expert lists
__global__ void router_kernel(const float* __restrict__ x,
                              const float* __restrict__ rDE) {
    int warp = (blockIdx.x * blockDim.x + threadIdx.x) >> 5;
    int lane = threadIdx.x & 31;
    if (warp >= TT) return;
    const float* xr = x + (size_t)warp * DDIM;

    float s[8] = {0.f,0.f,0.f,0.f,0.f,0.f,0.f,0.f};
    for (int d = lane; d < DDIM; d += 32) {
        float xv = xr[d];
        const float* rw = rDE + d * 8;
        float4 r0 = *(const float4*)(rw);
        float4 r1 = *(const float4*)(rw + 4);
        s[0] += xv * r0.x;  s[1] += xv * r0.y;
        s[2] += xv * r0.z;  s[3] += xv * r0.w;
        s[4] += xv * r1.x;  s[5] += xv * r1.y;
        s[6] += xv * r1.z;  s[7] += xv * r1.w;
    }
    #pragma unroll
    for (int off = 16; off > 0; off >>= 1) {
        #pragma unroll
        for (int e = 0; e < 8; ++e)
            s[e] += __shfl_xor_sync(0xffffffffu, s[e], off);
    }
    if (lane == 0) {
        int e1 = 0;
        #pragma unroll
        for (int e = 1; e < 8; ++e) if (s[e] > s[e1]) e1 = e;
        int e2 = (e1 == 0) ? 1 : 0;
        #pragma unroll
        for (int e = 0; e < 8; ++e) if (e != e1 && s[e] > s[e2]) e2 = e;
        float g1 = 1.f / (1.f + expf(-s[e1]));
        float g2 = 1.f / (1.f + expf(-s[e2]));
        int p1 = atomicAdd(&g_count[e1], 1);
        g_tok_list [e1 * TT + p1] = warp;
        g_gate_list[e1 * TT + p1] = g1;
        int p2 = atomicAdd(&g_count[e2], 1);
        g_tok_list [e2 * TT + p2] = warp;
        g_gate_list[e2 * TT + p2] = g2;
    }
}

// single block: padded prefix offsets, row-block->expert map, compacted arrays
__global__ void build_offsets_kernel() {
    __shared__ int sOff[NEXP];
    __shared__ int sCnt[NEXP];
    int tid = threadIdx.x;
    if (tid == 0) {
        int po = 0;
        for (int e = 0; e < NEXP; ++e) {
            int c = g_count[e];
            sCnt[e] = c;
            sOff[e] = po;
            int nrb = (c + 127) >> 7;
            for (int r = 0; r < nrb; ++r) g_rb_expert[(po >> 7) + r] = e;
            po += nrb << 7;
        }
        for (int rb = po >> 7; rb < NRB; ++rb) g_rb_expert[rb] = -1;
    }
    __syncthreads();
    for (int i = tid; i < NPAD; i += blockDim.x) {
        g_comp_tok[i]  = 0;
        g_comp_gate[i] = 0.f;
    }
    __syncthreads();
    for (int e = 0; e < NEXP; ++e) {
        int c = sCnt[e], o = sOff[e];
        for (int i = tid; i < c; i += blockDim.x) {
            g_comp_tok [o + i] = g_tok_list [e * TT + i];
            g_comp_gate[o + i] = g_gate_list[e * TT + i];
        }
    }
}

// materialize gated gathered token matrix (NPAD x D), fp16
__global__ void gather_scale_kernel(const float* __restrict__ x) {
    int row = blockIdx.x;
    int tok = g_comp_tok[row];
    float g  = g_comp_gate[row];
    const float4* src = (const float4*)(x + (size_t)tok * DDIM);
    uint2* dst = (uint2*)(g_gathA + (size_t)row * DDIM);
    for (int i = threadIdx.x; i < DDIM / 4; i += blockDim.x) {
        float4 v = src[i];
        __half2 h01 = __floats2half2_rn(v.x * g, v.y * g);
        __half2 h23 = __floats2half2_rn(v.z * g, v.w * g);
        uint2 u;
        u.x = *(uint32_t*)&h01;
        u.y = *(uint32_t*)&h23;
        dst[i] = u;
    }
}

// ---------------------------------------------------------------------------
// fp16 mma.sync GEMM (m16n8k16), ldmatrix x4, 4 warps (2x2), warp tile 64x64,
// block tile 128 rows x 128 B-rows, K-chunk 64 (4 k16 steps), 3-stage depth-2
// cp.async pipeline, 128 threads, 2 CTAs/SM. fp32 accumulation.
//   FUSE=1: B rows interleave w1/w3; epilogue stores act = half(silu(g)*u).
//   FUSE=0, EPI=0: float2 stores to float C (ld = N)
//   FUSE=0, EPI=1: atomicAdd into float C[rowTok[row]*N + col]
//   rbExpert != null: per-row-block expert weight base (skip blocks with -1)
// ---------------------------------------------------------------------------
template<int FUSE, int EPI>
__global__ void __launch_bounds__(128, 2)
mma_gemm_kernel(const __half* __restrict__ A, const __half* __restrict__ W,
                void* __restrict__ Cv, int N,
                const int* __restrict__ rbExpert, size_t wStride,
                const int* __restrict__ rowTok)
{
    extern __shared__ __half sm[];
    const int rowBase = blockIdx.y * 128;
    const int colBase = blockIdx.x * 128;

    const __half* Wb = W;
    if (rbExpert) {
        int e = rbExpert[blockIdx.y];
        if (e < 0) return;                 // fully-padded row block
        Wb += (size_t)e * wStride;
    }

    const int tid = threadIdx.x;
    const int wid = tid >> 5, lid = tid & 31;
    const int g = lid >> 2, tg = lid & 3;
    const int warpM = wid >> 1, warpN = wid & 1;

    const uint32_t smu = smem_u32(sm);

    auto load_stage = [&](int c, int st) {
        uint32_t base = smu + (uint32_t)st * (STG_H * 2);
        const __half* aG = A + (size_t)rowBase * 2048 + c * 64;
        #pragma unroll
        for (int s = 0; s < 8; ++s) {      // A: 128 rows x 8 16B segs
            int i = tid + s * 128, r = i >> 3, q = i & 7;
            cp16(base + (uint32_t)(r * SROW_H + q * 8) * 2,
                 aG + (size_t)r * 2048 + q * 8);
        }
        #pragma unroll
        for (int s = 0; s < 8; ++s) {      // B: 128 rows x 8 16B segs
            int i = tid + s * 128, r = i >> 3, q = i & 7;
            const __half* bsrc;
            if (FUSE) {
                bsrc = Wb + (size_t)((r & 1) * FDIM + (colBase >> 1) + (r >> 1)) * 2048
                          + c * 64 + q * 8;
            } else {
                bsrc = Wb + (size_t)(colBase + r) * 2048 + c * 64 + q * 8;
            }
            cp16(base + (uint32_t)(ASTG_H + r * SROW_H + q * 8) * 2, bsrc);
        }
        asm volatile("cp.async.commit_group;" ::: "memory");
    };

    load_stage(0, 0);
    load_stage(1, 1);

    float acc[4][8][4];
    #pragma unroll
    for (int mf = 0; mf < 4; ++mf)
        #pragma unroll
        for (int nf = 0; nf < 8; ++nf)
            #pragma unroll
            for (int j = 0; j < 4; ++j) acc[mf][nf][j] = 0.f;

    const uint32_t aThrOff =
        (uint32_t)(((warpM * 64 + (lid & 15)) * SROW_H + (lid >> 4) * 8) * 2);
    const uint32_t bThrOff =
        (uint32_t)((ASTG_H + (warpN * 64 + (lid & 15)) * SROW_H + (lid >> 4) * 8) * 2);

    for (int ck = 0; ck < NC; ++ck) {
        if (ck < NC - 2)       asm volatile("cp.async.wait_group 1;" ::: "memory");
        else                   asm volatile("cp.async.wait_group 0;" ::: "memory");
        __syncthreads();
        if (ck + 2 < NC) load_stage(ck + 2, (ck + 2) % NSTAGE);

        const uint32_t stB = smu + (uint32_t)(ck % NSTAGE) * (STG_H * 2);
        const uint32_t aB = stB + aThrOff;
        const uint32_t bB = stB + bThrOff;

        #pragma unroll
        for (int ks = 0; ks < 4; ++ks) {           // four k16 steps per chunk
            const uint32_t kByte = (uint32_t)(ks * 32);
            uint32_t a[4][4], b[8][2];
            #pragma unroll
            for (int mf = 0; mf < 4; ++mf)
                ldsm4(a[mf][0], a[mf][1], a[mf][2], a[mf][3],
                      aB + (uint32_t)(mf * 16 * SROW_H * 2) + kByte);
            #pragma unroll
            for (int j = 0; j < 4; ++j)
                ldsm4(b[2*j][0], b[2*j+1][0], b[2*j][1], b[2*j+1][1],
                      bB + (uint32_t)(j * 16 * SROW_H * 2) + kByte);
            #pragma unroll
            for (int mf = 0; mf < 4; ++mf)
                #pragma unroll
                for (int nf = 0; nf < 8; ++nf)
                    mma16(acc[mf][nf], a[mf], b[nf]);
        }
    }

    // epilogue
    const int rW = rowBase + warpM * 64;
    #pragma unroll
    for (int mf = 0; mf < 4; ++mf) {
        int r0 = rW + mf * 16 + g;
        int r1 = r0 + 8;
        if (FUSE) {
            __half* C = (__half*)Cv;
            #pragma unroll
            for (int nf = 0; nf < 8; ++nf) {
                int acol = (colBase >> 1) + warpN * 32 + nf * 4 + tg;
                float g0 = acc[mf][nf][0], u0 = acc[mf][nf][1];
                float g1 = acc[mf][nf][2], u1 = acc[mf][nf][3];
                C[(size_t)r0 * N + acol] =
                    __float2half_rn(g0 / (1.f + __expf(-g0)) * u0);
                C[(size_t)r1 * N + acol] =
                    __float2half_rn(g1 / (1.f + __expf(-g1)) * u1);
            }
        } else if (EPI == 0) {
            float* C = (float*)Cv;
            const int cW = colBase + warpN * 64;
            #pragma unroll
            for (int nf = 0; nf < 8; ++nf) {
                int col = cW + nf * 8 + tg * 2;
                *(float2*)(C + (size_t)r0 * N + col) =
                    make_float2(acc[mf][nf][0], acc[mf][nf][1]);
                *(float2*)(C + (size_t)r1 * N + col) =
                    make_float2(acc[mf][nf][2], acc[mf][nf][3]);
            }
        } else {
            float* C = (float*)Cv;
            const int cW = colBase + warpN * 64;
            int t0 = rowTok[r0];
            int t1 = rowTok[r1];
            #pragma unroll
            for (int nf = 0; nf < 8; ++nf) {
                int col = cW + nf * 8 + tg * 2;
                float* o0 = C + (size_t)t0 * N + col;
                float* o1 = C + (size_t)t1 * N + col;
                atomicAdd(o0 + 0, acc[mf][nf][0]);
                atomicAdd(o0 + 1, acc[mf][nf][1]);
                atomicAdd(o1 + 0, acc[mf][nf][2]);
                atomicAdd(o1 + 1, acc[mf][nf][3]);
            }
        }
    }
}

// ---------------------------------------------------------------------------
extern "C" void kernel_launch(void* const* d_in, const int* in_sizes, int n_in,
                              void* d_out, int out_size) {
    (void)in_sizes; (void)n_in; (void)out_size;
    const float* x    = (const float*)d_in[0];
    const float* rDE  = (const float*)d_in[1];
    const float* sw13 = (const float*)d_in[2];
    const float* sw2  = (const float*)d_in[3];
    const float* rw13 = (const float*)d_in[4];
    const float* rw2  = (const float*)d_in[5];
    float* out = (float*)d_out;

    __half *p_sact, *p_ract, *p_gathA, *p_xh, *p_w13h, *p_w2h, *p_rw13h, *p_rw2h;
    int *p_ctok, *p_rbe;
    cudaGetSymbolAddress((void**)&p_sact,  g_shared_act);
    cudaGetSymbolAddress((void**)&p_ract,  g_rout_act);
    cudaGetSymbolAddress((void**)&p_gathA, g_gathA);
    cudaGetSymbolAddress((void**)&p_xh,    g_xh);
    cudaGetSymbolAddress((void**)&p_w13h,  g_w13h);
    cudaGetSymbolAddress((void**)&p_w2h,   g_w2h);
    cudaGetSymbolAddress((void**)&p_rw13h, g_rw13h);
    cudaGetSymbolAddress((void**)&p_rw2h,  g_rw2h);
    cudaGetSymbolAddress((void**)&p_ctok,  g_comp_tok);
    cudaGetSymbolAddress((void**)&p_rbe,   g_rb_expert);

    cudaFuncSetAttribute(mma_gemm_kernel<1, 0>,
                         cudaFuncAttributeMaxDynamicSharedMemorySize, SMEM_BYTES);
    cudaFuncSetAttribute(mma_gemm_kernel<0, 0>,
                         cudaFuncAttributeMaxDynamicSharedMemorySize, SMEM_BYTES);
    cudaFuncSetAttribute(mma_gemm_kernel<0, 1>,
                         cudaFuncAttributeMaxDynamicSharedMemorySize, SMEM_BYTES);

    // R9 champion structure, minus the standalone zero_counts launch
    cvt_half_kernel<1><<<2048, 256>>>((const float4*)x,    (uint2*)p_xh,   TT * DDIM / 4);
    cvt_half_kernel<0><<<2048, 256>>>((const float4*)sw13, (uint2*)p_w13h, TWO_F * DDIM / 4);
    cvt_half_kernel<0><<<2048, 256>>>((const float4*)sw2,  (uint2*)p_w2h,  DDIM * FDIM / 4);
    // shared expert GEMM1 + fused swiglu: act = swiglu(x @ w13^T)
    mma_gemm_kernel<1, 0><<<dim3(TWO_F / 128, TT / 128), 128, SMEM_BYTES>>>(
        p_xh, p_w13h, p_sact, FDIM, nullptr, 0, nullptr);
    // shared expert GEMM2: out = act @ w2^T  (writes every output element)
    mma_gemm_kernel<0, 0><<<dim3(DDIM / 128, TT / 128), 128, SMEM_BYTES>>>(
        p_sact, p_w2h, out, DDIM, nullptr, 0, nullptr);

    router_kernel<<<TT / 8, 256>>>(x, rDE);
    build_offsets_kernel<<<1, 256>>>();
    gather_scale_kernel<<<NPAD, 256>>>(x);
    cvt_half_kernel<0><<<4096, 256>>>((const float4*)rw13, (uint2*)p_rw13h, NEXP * TWO_F * DDIM / 4);
    cvt_half_kernel<0><<<4096, 256>>>((const float4*)rw2,  (uint2*)p_rw2h,  NEXP * DDIM * FDIM / 4);

    // routed GEMM1 + fused swiglu: act = swiglu(gathA @ w13_e^T)
    mma_gemm_kernel<1, 0><<<dim3(TWO_F / 128, NRB), 128, SMEM_BYTES>>>(
        p_gathA, p_rw13h, p_ract, FDIM, p_rbe, (size_t)TWO_F * DDIM, nullptr);
    // routed GEMM2: out[tok] += act @ w2_e^T  (atomic scatter)
    mma_gemm_kernel<0, 1><<<dim3(DDIM / 128, NRB), 128, SMEM_BYTES>>>(
        p_ract, p_rw2h, out, DDIM, p_rbe, (size_t)DDIM * FDIM, p_ctok);
}

// round 16
// speedup vs baseline: 1.5410x; 1.0125x over previous
#include <cuda_runtime.h>
#include <cuda_fp16.h>
#include <math.h>
#include <stdint.h>

// ---------------------------------------------------------------------------
// Problem constants: B=2, T=2048 -> Tt=4096 tokens, D=2048, F=2048, E=8, K=2
// All four GEMMs share K = 2048.
// ---------------------------------------------------------------------------
#define TT      4096
#define DDIM    2048
#define FDIM    2048
#define TWO_F   4096
#define NEXP    8
#define NPAD    9216          // 72 row-blocks of 128 (8192 assignments + padding)
#define NRB     72

#define NC      32            // K chunks (2048 / 64)
#define SROW_H  72            // padded smem row stride (halves): 144B/row
#define ASTG_H  (128 * SROW_H)   // A stage halves (128 rows)
#define BSTG_H  (128 * SROW_H)   // B stage halves (128 rows)
#define STG_H   (ASTG_H + BSTG_H)
#define NSTAGE  3
#define SMEM_BYTES (NSTAGE * STG_H * 2)   // 110592 -> 2 CTAs/SM

// ------------------------- device scratch (no cudaMalloc allowed) ----------
__device__ __half g_shared_act[(size_t)TT * FDIM];       // 16 MB
__device__ __half g_rout_act  [(size_t)NPAD * FDIM];     // 36 MB
__device__ __half g_gathA     [(size_t)NPAD * DDIM];     // 36 MB
__device__ __half g_xh        [(size_t)TT * DDIM];       // 16 MB (fp16 x)
__device__ __half g_w13h      [(size_t)TWO_F * DDIM];    // 16 MB
__device__ __half g_w2h       [(size_t)DDIM * FDIM];     // 8 MB
__device__ __half g_rw13h     [(size_t)NEXP * TWO_F * DDIM];  // 128 MB
__device__ __half g_rw2h      [(size_t)NEXP * DDIM * FDIM];   // 64 MB
__device__ int    g_count[NEXP];
__device__ int    g_tok_list [NEXP * TT];
__device__ float  g_gate_list[NEXP * TT];
__device__ int    g_comp_tok [NPAD];
__device__ float  g_comp_gate[NPAD];
__device__ int    g_rb_expert[NRB];

// ------------------------- helpers -----------------------------------------
__device__ __forceinline__ uint32_t smem_u32(const void* p) {
    uint32_t a;
    asm("{ .reg .u64 t; cvta.to.shared.u64 t, %1; cvt.u32.u64 %0, t; }"
        : "=r"(a) : "l"(p));
    return a;
}
__device__ __forceinline__ void cp16(uint32_t dst, const void* src) {
    asm volatile("cp.async.cg.shared.global [%0], [%1], 16;" :: "r"(dst), "l"(src));
}
__device__ __forceinline__ void mma16(float* c, const uint32_t* a, const uint32_t* b) {
    asm volatile("mma.sync.aligned.m16n8k16.row.col.f32.f16.f16.f32 "
                 "{%0,%1,%2,%3}, {%4,%5,%6,%7}, {%8,%9}, {%0,%1,%2,%3};"
                 : "+f"(c[0]), "+f"(c[1]), "+f"(c[2]), "+f"(c[3])
                 : "r"(a[0]), "r"(a[1]), "r"(a[2]), "r"(a[3]),
                   "r"(b[0]), "r"(b[1]));
}
__device__ __forceinline__ void ldsm4(uint32_t& r0, uint32_t& r1,
                                      uint32_t& r2, uint32_t& r3, uint32_t addr) {
    asm volatile("ldmatrix.sync.aligned.m8n8.x4.shared.b16 {%0,%1,%2,%3}, [%4];"
                 : "=r"(r0), "=r"(r1), "=r"(r2), "=r"(r3) : "r"(addr));
}

// ------------------------- small kernels -----------------------------------
// fp32 -> fp16 (RN) conversion. ZERO=1: block 0 also clears g_count.
template<int ZERO>
__global__ void cvt_half_kernel(const float4* __restrict__ in,
                                uint2* __restrict__ o, int n4) {
    if (ZERO && blockIdx.x == 0 && threadIdx.x < NEXP) g_count[threadIdx.x] = 0;
    int stride = gridDim.x * blockDim.x;
    for (int i = blockIdx.x * blockDim.x + threadIdx.x; i < n4; i += stride) {
        float4 v = in[i];
        __half2 h01 = __floats2half2_rn(v.x, v.y);
        __half2 h23 = __floats2half2_rn(v.z, v.w);
        uint2 u;
        u.x = *(uint32_t*)&h01;
        u.y = *(uint32_t*)&h23;
        o[i] = u;
    }
}

// one warp per token: 8 scores, sigmoid top-2, compact into per-expert lists
__global__ void router_kernel(const float* __restrict__ x,
                              const float* __restrict__ rDE) {
    int warp = (blockIdx.x * blockDim.x + threadIdx.x) >> 5;
    int lane = threadIdx.x & 31;
    if (warp >= TT) return;
    const float* xr = x + (size_t)warp * DDIM;

    float s[8] = {0.f,0.f,0.f,0.f,0.f,0.f,0.f,0.f};
    for (int d = lane; d < DDIM; d += 32) {
        float xv = xr[d];
        const float* rw = rDE + d * 8;
        float4 r0 = *(const float4*)(rw);
        float4 r1 = *(const float4*)(rw + 4);
        s[0] += xv * r0.x;  s[1] += xv * r0.y;
        s[2] += xv * r0.z;  s[3] += xv * r0.w;
        s[4] += xv * r1.x;  s[5] += xv * r1.y;
        s[6] += xv * r1.z;  s[7] += xv * r1.w;
    }
    #pragma unroll
    for (int off = 16; off > 0; off >>= 1) {
        #pragma unroll
        for (int e = 0; e < 8; ++e)
            s[e] += __shfl_xor_sync(0xffffffffu, s[e], off);
    }
    if (lane == 0) {
        int e1 = 0;
        #pragma unroll
        for (int e = 1; e < 8; ++e) if (s[e] > s[e1]) e1 = e;
        int e2 = (e1 == 0) ? 1 : 0;
        #pragma unroll
        for (int e = 0; e < 8; ++e) if (e != e1 && s[e] > s[e2]) e2 = e;
        float g1 = 1.f / (1.f + expf(-s[e1]));
        float g2 = 1.f / (1.f + expf(-s[e2]));
        int p1 = atomicAdd(&g_count[e1], 1);
        g_tok_list [e1 * TT + p1] = warp;
        g_gate_list[e1 * TT + p1] = g1;
        int p2 = atomicAdd(&g_count[e2], 1);
        g_tok_list [e2 * TT + p2] = warp;
        g_gate_list[e2 * TT + p2] = g2;
    }
}

// single block: padded prefix offsets, row-block->expert map, compacted arrays
__global__ void build_offsets_kernel() {
    __shared__ int sOff[NEXP];
    __shared__ int sCnt[NEXP];
    int tid = threadIdx.x;
    if (tid == 0) {
        int po = 0;
        for (int e = 0; e < NEXP; ++e) {
            int c = g_count[e];
            sCnt[e] = c;
            sOff[e] = po;
            int nrb = (c + 127) >> 7;
            for (int r = 0; r < nrb; ++r) g_rb_expert[(po >> 7) + r] = e;
            po += nrb << 7;
        }
        for (int rb = po >> 7; rb < NRB; ++rb) g_rb_expert[rb] = -1;
    }
    __syncthreads();
    for (int i = tid; i < NPAD; i += blockDim.x) {
        g_comp_tok[i]  = 0;
        g_comp_gate[i] = 0.f;
    }
    __syncthreads();
    for (int e = 0; e < NEXP; ++e) {
        int c = sCnt[e], o = sOff[e];
        for (int i = tid; i < c; i += blockDim.x) {
            g_comp_tok [o + i] = g_tok_list [e * TT + i];
            g_comp_gate[o + i] = g_gate_list[e * TT + i];
        }
    }
}

// materialize gated gathered token matrix (NPAD x D), fp16
__global__ void gather_scale_kernel(const float* __restrict__ x) {
    int row = blockIdx.x;
    int tok = g_comp_tok[row];
    float g  = g_comp_gate[row];
    const float4* src = (const float4*)(x + (size_t)tok * DDIM);
    uint2* dst = (uint2*)(g_gathA + (size_t)row * DDIM);
    for (int i = threadIdx.x; i < DDIM / 4; i += blockDim.x) {
        float4 v = src[i];
        __half2 h01 = __floats2half2_rn(v.x * g, v.y * g);
        __half2 h23 = __floats2half2_rn(v.z * g, v.w * g);
        uint2 u;
        u.x = *(uint32_t*)&h01;
        u.y = *(uint32_t*)&h23;
        dst[i] = u;
    }
}

// ---------------------------------------------------------------------------
// fp16 mma.sync GEMM (m16n8k16), ldmatrix x4, 8 warps (2x4), warp tile 64x32,
// block tile 128 rows x 128 B-rows, K-chunk 64 (4 k16 steps), 3-stage depth-2
// cp.async pipeline, 256 threads, 2 CTAs/SM (16 warps/SM for latency hiding;
// ncu showed tensor=49%, occ=11.8% with the 4-warp variant — nothing
// saturated, pure latency deficit).  fp32 accumulation.
//   FUSE=1: B rows interleave w1/w3; epilogue stores act = half(silu(g)*u).
//   FUSE=0, EPI=0: float2 stores to float C (ld = N)
//   FUSE=0, EPI=1: atomicAdd into float C[rowTok[row]*N + col]
//   rbExpert != null: per-row-block expert weight base (skip blocks with -1)
// ---------------------------------------------------------------------------
template<int FUSE, int EPI>
__global__ void __launch_bounds__(256, 2)
mma_gemm_kernel(const __half* __restrict__ A, const __half* __restrict__ W,
                void* __restrict__ Cv, int N,
                const int* __restrict__ rbExpert, size_t wStride,
                const int* __restrict__ rowTok)
{
    extern __shared__ __half sm[];
    const int rowBase = blockIdx.y * 128;
    const int colBase = blockIdx.x * 128;

    const __half* Wb = W;
    if (rbExpert) {
        int e = rbExpert[blockIdx.y];
        if (e < 0) return;                 // fully-padded row block
        Wb += (size_t)e * wStride;
    }

    const int tid = threadIdx.x;
    const int wid = tid >> 5, lid = tid & 31;
    const int g = lid >> 2, tg = lid & 3;
    const int warpM = wid >> 2, warpN = wid & 3;   // 2 x 4 warp grid

    const uint32_t smu = smem_u32(sm);

    auto load_stage = [&](int c, int st) {
        uint32_t base = smu + (uint32_t)st * (STG_H * 2);
        const __half* aG = A + (size_t)rowBase * 2048 + c * 64;
        #pragma unroll
        for (int s = 0; s < 4; ++s) {      // A: 128 rows x 8 16B segs
            int i = tid + s * 256, r = i >> 3, q = i & 7;
            cp16(base + (uint32_t)(r * SROW_H + q * 8) * 2,
                 aG + (size_t)r * 2048 + q * 8);
        }
        #pragma unroll
        for (int s = 0; s < 4; ++s) {      // B: 128 rows x 8 16B segs
            int i = tid + s * 256, r = i >> 3, q = i & 7;
            const __half* bsrc;
            if (FUSE) {
                bsrc = Wb + (size_t)((r & 1) * FDIM + (colBase >> 1) + (r >> 1)) * 2048
                          + c * 64 + q * 8;
            } else {
                bsrc = Wb + (size_t)(colBase + r) * 2048 + c * 64 + q * 8;
            }
            cp16(base + (uint32_t)(ASTG_H + r * SROW_H + q * 8) * 2, bsrc);
        }
        asm volatile("cp.async.commit_group;" ::: "memory");
    };

    load_stage(0, 0);
    load_stage(1, 1);

    float acc[4][4][4];
    #pragma unroll
    for (int mf = 0; mf < 4; ++mf)
        #pragma unroll
        for (int nf = 0; nf < 4; ++nf)
            #pragma unroll
            for (int j = 0; j < 4; ++j) acc[mf][nf][j] = 0.f;

    const uint32_t aThrOff =
        (uint32_t)(((warpM * 64 + (lid & 15)) * SROW_H + (lid >> 4) * 8) * 2);
    const uint32_t bThrOff =
        (uint32_t)((ASTG_H + (warpN * 32 + (lid & 15)) * SROW_H + (lid >> 4) * 8) * 2);

    for (int ck = 0; ck < NC; ++ck) {
        if (ck < NC - 2)       asm volatile("cp.async.wait_group 1;" ::: "memory");
        else                   asm volatile("cp.async.wait_group 0;" ::: "memory");
        __syncthreads();
        if (ck + 2 < NC) load_stage(ck + 2, (ck + 2) % NSTAGE);

        const uint32_t stB = smu + (uint32_t)(ck % NSTAGE) * (STG_H * 2);
        const uint32_t aB = stB + aThrOff;
        const uint32_t bB = stB + bThrOff;

        #pragma unroll
        for (int ks = 0; ks < 4; ++ks) {           // four k16 steps per chunk
            const uint32_t kByte = (uint32_t)(ks * 32);
            uint32_t a[4][4], b[4][2];
            #pragma unroll
            for (int mf = 0; mf < 4; ++mf)
                ldsm4(a[mf][0], a[mf][1], a[mf][2], a[mf][3],
                      aB + (uint32_t)(mf * 16 * SROW_H * 2) + kByte);
            #pragma unroll
            for (int j = 0; j < 2; ++j)
                ldsm4(b[2*j][0], b[2*j+1][0], b[2*j][1], b[2*j+1][1],
                      bB + (uint32_t)(j * 16 * SROW_H * 2) + kByte);
            #pragma unroll
            for (int mf = 0; mf < 4; ++mf)
                #pragma unroll
                for (int nf = 0; nf < 4; ++nf)
                    mma16(acc[mf][nf], a[mf], b[nf]);
        }
    }

    // epilogue (warp covers rows warpM*64..+63, B-rows warpN*32..+31)
    const int rW = rowBase + warpM * 64;
    #pragma unroll
    for (int mf = 0; mf < 4; ++mf) {
        int r0 = rW + mf * 16 + g;
        int r1 = r0 + 8;
        if (FUSE) {
            __half* C = (__half*)Cv;
            #pragma unroll
            for (int nf = 0; nf < 4; ++nf) {
                int acol = (colBase >> 1) + warpN * 16 + nf * 4 + tg;
                float g0 = acc[mf][nf][0], u0 = acc[mf][nf][1];
                float g1 = acc[mf][nf][2], u1 = acc[mf][nf][3];
                C[(size_t)r0 * N + acol] =
                    __float2half_rn(g0 / (1.f + __expf(-g0)) * u0);
                C[(size_t)r1 * N + acol] =
                    __float2half_rn(g1 / (1.f + __expf(-g1)) * u1);
            }
        } else if (EPI == 0) {
            float* C = (float*)Cv;
            const int cW = colBase + warpN * 32;
            #pragma unroll
            for (int nf = 0; nf < 4; ++nf) {
                int col = cW + nf * 8 + tg * 2;
                *(float2*)(C + (size_t)r0 * N + col) =
                    make_float2(acc[mf][nf][0], acc[mf][nf][1]);
                *(float2*)(C + (size_t)r1 * N + col) =
                    make_float2(acc[mf][nf][2], acc[mf][nf][3]);
            }
        } else {
            float* C = (float*)Cv;
            const int cW = colBase + warpN * 32;
            int t0 = rowTok[r0];
            int t1 = rowTok[r1];
            #pragma unroll
            for (int nf = 0; nf < 4; ++nf) {
                int col = cW + nf * 8 + tg * 2;
                float* o0 = C + (size_t)t0 * N + col;
                float* o1 = C + (size_t)t1 * N + col;
                atomicAdd(o0 + 0, acc[mf][nf][0]);
                atomicAdd(o0 + 1, acc[mf][nf][1]);
                atomicAdd(o1 + 0, acc[mf][nf][2]);
                atomicAdd(o1 + 1, acc[mf][nf][3]);
            }
        }
    }
}

// ---------------------------------------------------------------------------
extern "C" void kernel_launch(void* const* d_in, const int* in_sizes, int n_in,
                              void* d_out, int out_size) {
    (void)in_sizes; (void)n_in; (void)out_size;
    const float* x    = (const float*)d_in[0];
    const float* rDE  = (const float*)d_in[1];
    const float* sw13 = (const float*)d_in[2];
    const float* sw2  = (const float*)d_in[3];
    const float* rw13 = (const float*)d_in[4];
    const float* rw2  = (const float*)d_in[5];
    float* out = (float*)d_out;

    __half *p_sact, *p_ract, *p_gathA, *p_xh, *p_w13h, *p_w2h, *p_rw13h, *p_rw2h;
    int *p_ctok, *p_rbe;
    cudaGetSymbolAddress((void**)&p_sact,  g_shared_act);
    cudaGetSymbolAddress((void**)&p_ract,  g_rout_act);
    cudaGetSymbolAddress((void**)&p_gathA, g_gathA);
    cudaGetSymbolAddress((void**)&p_xh,    g_xh);
    cudaGetSymbolAddress((void**)&p_w13h,  g_w13h);
    cudaGetSymbolAddress((void**)&p_w2h,   g_w2h);
    cudaGetSymbolAddress((void**)&p_rw13h, g_rw13h);
    cudaGetSymbolAddress((void**)&p_rw2h,  g_rw2h);
    cudaGetSymbolAddress((void**)&p_ctok,  g_comp_tok);
    cudaGetSymbolAddress((void**)&p_rbe,   g_rb_expert);

    cudaFuncSetAttribute(mma_gemm_kernel<1, 0>,
                         cudaFuncAttributeMaxDynamicSharedMemorySize, SMEM_BYTES);
    cudaFuncSetAttribute(mma_gemm_kernel<0, 0>,
                         cudaFuncAttributeMaxDynamicSharedMemorySize, SMEM_BYTES);
    cudaFuncSetAttribute(mma_gemm_kernel<0, 1>,
                         cudaFuncAttributeMaxDynamicSharedMemorySize, SMEM_BYTES);

    // champion launch structure (R14)
    cvt_half_kernel<1><<<2048, 256>>>((const float4*)x,    (uint2*)p_xh,   TT * DDIM / 4);
    cvt_half_kernel<0><<<2048, 256>>>((const float4*)sw13, (uint2*)p_w13h, TWO_F * DDIM / 4);
    cvt_half_kernel<0><<<2048, 256>>>((const float4*)sw2,  (uint2*)p_w2h,  DDIM * FDIM / 4);
    // shared expert GEMM1 + fused swiglu: act = swiglu(x @ w13^T)
    mma_gemm_kernel<1, 0><<<dim3(TWO_F / 128, TT / 128), 256, SMEM_BYTES>>>(
        p_xh, p_w13h, p_sact, FDIM, nullptr, 0, nullptr);
    // shared expert GEMM2: out = act @ w2^T  (writes every output element)
    mma_gemm_kernel<0, 0><<<dim3(DDIM / 128, TT / 128), 256, SMEM_BYTES>>>(
        p_sact, p_w2h, out, DDIM, nullptr, 0, nullptr);

    router_kernel<<<TT / 8, 256>>>(x, rDE);
    build_offsets_kernel<<<1, 256>>>();
    gather_scale_kernel<<<NPAD, 256>>>(x);
    cvt_half_kernel<0><<<4096, 256>>>((const float4*)rw13, (uint2*)p_rw13h, NEXP * TWO_F * DDIM / 4);
    cvt_half_kernel<0><<<4096, 256>>>((const float4*)rw2,  (uint2*)p_rw2h,  NEXP * DDIM * FDIM / 4);

    // routed GEMM1 + fused swiglu: act = swiglu(gathA @ w13_e^T)
    mma_gemm_kernel<1, 0><<<dim3(TWO_F / 128, NRB), 256, SMEM_BYTES>>>(
        p_gathA, p_rw13h, p_ract, FDIM, p_rbe, (size_t)TWO_F * DDIM, nullptr);
    // routed GEMM2: out[tok] += act @ w2_e^T  (atomic scatter)
    mma_gemm_kernel<0, 1><<<dim3(DDIM / 128, NRB), 256, SMEM_BYTES>>>(
        p_ract, p_rw2h, out, DDIM, p_rbe, (size_t)DDIM * FDIM, p_ctok);
}